// round 5
// baseline (speedup 1.0000x reference)
#include <cuda_runtime.h>
#include <cuda_bf16.h>

// TensorProductScatter, round 2 design: in-kernel CSR-by-dst, then warp-per-dst
// register accumulation with plain stores. Eliminates the 1.13 GB of L2 atomic
// RMW traffic that co-bound the R1 kernel (DRAM 59.8% / L2 60.2%).
//
// Pipeline (all inside one graph-captured kernel_launch):
//   k0: zero per-dst counters
//   k1: histogram  counts[dst]++
//   k2: single-block scan -> offsets (and wptr copy)
//   k3: fill       perm[atomicAdd(wptr[dst])] = e
//   k4: consumer   warp per dst: accumulate tensor product over its edge list
//                  in 11 regs/lane, stage in smem, store 88 float4 (write-only)

#define MULC 32
#define ROWF 352            // 32 + 96 + 96 + 32 + 96
#define WARPS_PER_BLOCK 8
#define MAX_E 800000
#define MAX_N 50000

__device__ int d_counts[MAX_N];
__device__ int d_offsets[MAX_N + 1];
__device__ int d_wptr[MAX_N];
__device__ int d_perm[MAX_E];

// ---------------- preprocessing ----------------

__global__ void tps_zero_counts(int N) {
    int i = blockIdx.x * blockDim.x + threadIdx.x;
    if (i < N) d_counts[i] = 0;
}

__global__ void tps_hist(const int* __restrict__ edge_dst, int E) {
    int e = blockIdx.x * blockDim.x + threadIdx.x;
    if (e < E) atomicAdd(&d_counts[edge_dst[e]], 1);
}

__global__ __launch_bounds__(1024) void tps_scan(int N) {
    __shared__ int partial[1024];
    const int t = threadIdx.x;
    const int chunk = (N + 1023) / 1024;
    const int start = t * chunk;
    const int end   = min(start + chunk, N);

    int sum = 0;
    for (int i = start; i < end; i++) sum += d_counts[i];
    partial[t] = sum;
    __syncthreads();
    // Hillis-Steele inclusive scan over 1024 partials
    for (int dstp = 1; dstp < 1024; dstp <<= 1) {
        int v = (t >= dstp) ? partial[t - dstp] : 0;
        __syncthreads();
        partial[t] += v;
        __syncthreads();
    }
    int run = (t == 0) ? 0 : partial[t - 1];
    for (int i = start; i < end; i++) {
        d_offsets[i] = run;
        d_wptr[i]    = run;
        run += d_counts[i];
    }
    if (end >= N) d_offsets[N] = run;  // all qualifying threads write the total
}

__global__ void tps_fill(const int* __restrict__ edge_dst, int E) {
    int e = blockIdx.x * blockDim.x + threadIdx.x;
    if (e < E) {
        int pos = atomicAdd(&d_wptr[edge_dst[e]], 1);
        d_perm[pos] = e;
    }
}

// ---------------- consumer: warp per destination node ----------------

__global__ __launch_bounds__(WARPS_PER_BLOCK * 32)
void tps_csr_kernel(const float* __restrict__ x,
                    const float* __restrict__ edge_attr,
                    const float* __restrict__ edge_weight,
                    const int*   __restrict__ edge_src,
                    float*       __restrict__ out,
                    int N) {
    __shared__ __align__(16) float sm[WARPS_PER_BLOCK][ROWF];

    const int wb   = threadIdx.x >> 5;
    const int lane = threadIdx.x & 31;
    const int d    = blockIdx.x * WARPS_PER_BLOCK + wb;
    if (d >= N) return;

    const int beg = d_offsets[d];
    const int end = d_offsets[d + 1];

    const float INV_SQRT3 = 0.5773502691896258f;   // 1/sqrt(3)
    const float INV_SQRT2 = 0.7071067811865476f;   // 1/sqrt(2)

    float acc0  = 0.f;
    float acc1x = 0.f, acc1y = 0.f, acc1z = 0.f;
    float acc2x = 0.f, acc2y = 0.f, acc2z = 0.f;
    float acc3  = 0.f;
    float acc4x = 0.f, acc4y = 0.f, acc4z = 0.f;

    for (int i = beg; i < end; i++) {
        const int e = d_perm[i];                    // warp-uniform broadcast
        const int s = edge_src[e];

        const float4 a = *reinterpret_cast<const float4*>(edge_attr + 4LL * e);
        const float a0 = a.x, a1x = a.y, a1y = a.z, a1z = a.w;

        // x gather: L2-resident table (25.6 MB)
        const float* xrow = x + (long long)s * (4 * MULC);
        const float xs0 = __ldg(xrow + lane);
        const float x1a = __ldg(xrow + MULC + 3 * lane + 0);
        const float x1b = __ldg(xrow + MULC + 3 * lane + 1);
        const float x1c = __ldg(xrow + MULC + 3 * lane + 2);

        // streaming weights (read-once: evict-first)
        const float* wrow = edge_weight + (long long)e * (5 * MULC);
        const float w0 = __ldcs(wrow + 0 * MULC + lane);
        const float w1 = __ldcs(wrow + 1 * MULC + lane);
        const float w2 = __ldcs(wrow + 2 * MULC + lane);
        const float w3 = __ldcs(wrow + 3 * MULC + lane);
        const float w4 = __ldcs(wrow + 4 * MULC + lane);

        acc0 += w0 * xs0 * a0;

        const float w1x = w1 * xs0;
        acc1x += w1x * a1x;  acc1y += w1x * a1y;  acc1z += w1x * a1z;

        const float w2a = w2 * a0;
        acc2x += w2a * x1a;  acc2y += w2a * x1b;  acc2z += w2a * x1c;

        const float dot = x1a * a1x + x1b * a1y + x1c * a1z;
        acc3 += w3 * dot * INV_SQRT3;

        const float cx = x1b * a1z - x1c * a1y;
        const float cy = x1c * a1x - x1a * a1z;
        const float cz = x1a * a1y - x1b * a1x;
        const float w4s = w4 * INV_SQRT2;
        acc4x += w4s * cx;  acc4y += w4s * cy;  acc4z += w4s * cz;
    }

    // Stage row (stride-3: gcd(3,32)=1 -> conflict-free), then coalesced store
    float* r = sm[wb];
    r[lane]                = acc0;
    r[MULC + 3 * lane + 0] = acc1x;
    r[MULC + 3 * lane + 1] = acc1y;
    r[MULC + 3 * lane + 2] = acc1z;
    r[128  + 3 * lane + 0] = acc2x;
    r[128  + 3 * lane + 1] = acc2y;
    r[128  + 3 * lane + 2] = acc2z;
    r[224  + lane]         = acc3;
    r[256  + 3 * lane + 0] = acc4x;
    r[256  + 3 * lane + 1] = acc4y;
    r[256  + 3 * lane + 2] = acc4z;
    __syncwarp();

    const float4* rv = reinterpret_cast<const float4*>(r);
    float4* orow = reinterpret_cast<float4*>(out + (long long)d * ROWF);
    #pragma unroll
    for (int c = lane; c < ROWF / 4; c += 32) {
        orow[c] = rv[c];
    }
}

// ---------------- launch ----------------

extern "C" void kernel_launch(void* const* d_in, const int* in_sizes, int n_in,
                              void* d_out, int out_size) {
    const float* x           = (const float*)d_in[0];
    const float* edge_attr   = (const float*)d_in[1];
    const float* edge_weight = (const float*)d_in[2];
    const int*   edge_dst    = (const int*)d_in[3];
    const int*   edge_src    = (const int*)d_in[4];
    float* out = (float*)d_out;

    const int E = in_sizes[3];          // edges
    const int N = out_size / ROWF;      // destination nodes

    tps_zero_counts<<<(N + 255) / 256, 256>>>(N);
    tps_hist<<<(E + 255) / 256, 256>>>(edge_dst, E);
    tps_scan<<<1, 1024>>>(N);
    tps_fill<<<(E + 255) / 256, 256>>>(edge_dst, E);

    int blocks = (N + WARPS_PER_BLOCK - 1) / WARPS_PER_BLOCK;
    tps_csr_kernel<<<blocks, WARPS_PER_BLOCK * 32>>>(
        x, edge_attr, edge_weight, edge_src, out, N);
}

// round 6
// speedup vs baseline: 1.0716x; 1.0716x over previous
#include <cuda_runtime.h>
#include <cuda_bf16.h>

// TensorProductScatter: per-edge e3nn tensor product + scatter-add.
// Back to the atomic warp-per-edge design (R1, 234us), with the L1tex fix:
// the x[src] row (512 B) is fetched as ONE warp-wide float4 load (4 L1
// wavefronts) and transposed through SMEM, instead of 4 scalar gathers whose
// stride-3 pattern cost 10 wavefronts re-touching the same lines.
// Flush uses red.global.add.v4.f32 (16B vector reductions).

#define MULC 32
#define ROWF 352            // 32 + 96 + 96 + 32 + 96
#define WARPS_PER_BLOCK 8

__device__ __forceinline__ void red_add_v4(float* p, float4 v) {
    asm volatile("red.global.add.v4.f32 [%0], {%1, %2, %3, %4};"
                 :: "l"(p), "f"(v.x), "f"(v.y), "f"(v.z), "f"(v.w)
                 : "memory");
}

__global__ void tps_zero_kernel(float4* __restrict__ out, int n4) {
    int i = blockIdx.x * blockDim.x + threadIdx.x;
    if (i < n4) out[i] = make_float4(0.f, 0.f, 0.f, 0.f);
}

__global__ __launch_bounds__(WARPS_PER_BLOCK * 32)
void tps_scatter_kernel(const float* __restrict__ x,
                        const float* __restrict__ edge_attr,
                        const float* __restrict__ edge_weight,
                        const int*   __restrict__ edge_dst,
                        const int*   __restrict__ edge_src,
                        float*       __restrict__ out,
                        int E) {
    // Per-warp staging: 128 floats for the gathered x row + 352 for the output row
    __shared__ __align__(16) float sm_x[WARPS_PER_BLOCK][4 * MULC];
    __shared__ __align__(16) float sm_o[WARPS_PER_BLOCK][ROWF];

    const int wb   = threadIdx.x >> 5;
    const int lane = threadIdx.x & 31;
    const long long e = (long long)blockIdx.x * WARPS_PER_BLOCK + wb;
    if (e >= E) return;

    // Uniform (warp-broadcast) loads
    const int s = edge_src[e];
    const int d = edge_dst[e];
    const float4 a = *reinterpret_cast<const float4*>(edge_attr + 4 * e);
    const float a0 = a.x, a1x = a.y, a1y = a.z, a1z = a.w;

    // Streaming weight loads (read-once: evict-first, protect L2 for x + out)
    const float* wrow = edge_weight + e * (5 * MULC);
    const float w0 = __ldcs(wrow + 0 * MULC + lane);
    const float w1 = __ldcs(wrow + 1 * MULC + lane);
    const float w2 = __ldcs(wrow + 2 * MULC + lane);
    const float w3 = __ldcs(wrow + 3 * MULC + lane);
    const float w4 = __ldcs(wrow + 4 * MULC + lane);

    // Gather the full 512 B x row with ONE vector load (4 L1 wavefronts),
    // transpose through SMEM into channel order.
    const float4 xq = __ldg(reinterpret_cast<const float4*>(x + (long long)s * (4 * MULC)) + lane);
    float* xs = sm_x[wb];
    reinterpret_cast<float4*>(xs)[lane] = xq;
    __syncwarp();

    const float xs0 = xs[lane];
    const float x1a = xs[MULC + 3 * lane + 0];   // stride-3 LDS: conflict-free
    const float x1b = xs[MULC + 3 * lane + 1];
    const float x1c = xs[MULC + 3 * lane + 2];

    const float INV_SQRT3 = 0.5773502691896258f;   // 1/sqrt(3)
    const float INV_SQRT2 = 0.7071067811865476f;   // 1/sqrt(2)

    const float o0 = w0 * xs0 * a0;

    const float w1x = w1 * xs0;
    const float o1x = w1x * a1x, o1y = w1x * a1y, o1z = w1x * a1z;

    const float w2a = w2 * a0;
    const float o2x = w2a * x1a, o2y = w2a * x1b, o2z = w2a * x1c;

    const float dot = x1a * a1x + x1b * a1y + x1c * a1z;
    const float o3 = w3 * dot * INV_SQRT3;

    const float cx = x1b * a1z - x1c * a1y;
    const float cy = x1c * a1x - x1a * a1z;
    const float cz = x1a * a1y - x1b * a1x;
    const float w4s = w4 * INV_SQRT2;
    const float o4x = w4s * cx, o4y = w4s * cy, o4z = w4s * cz;

    // Stage the 352-float row (stride-3 stores conflict-free), then flush with
    // coalesced 16B vector reductions.
    float* r = sm_o[wb];
    r[lane]                = o0;
    r[MULC + 3 * lane + 0] = o1x;
    r[MULC + 3 * lane + 1] = o1y;
    r[MULC + 3 * lane + 2] = o1z;
    r[128  + 3 * lane + 0] = o2x;
    r[128  + 3 * lane + 1] = o2y;
    r[128  + 3 * lane + 2] = o2z;
    r[224  + lane]         = o3;
    r[256  + 3 * lane + 0] = o4x;
    r[256  + 3 * lane + 1] = o4y;
    r[256  + 3 * lane + 2] = o4z;
    __syncwarp();

    const float4* rv = reinterpret_cast<const float4*>(r);
    float* orow = out + (long long)d * ROWF;
    #pragma unroll
    for (int c = lane; c < ROWF / 4; c += 32) {
        red_add_v4(orow + 4 * c, rv[c]);
    }
}

extern "C" void kernel_launch(void* const* d_in, const int* in_sizes, int n_in,
                              void* d_out, int out_size) {
    const float* x           = (const float*)d_in[0];
    const float* edge_attr   = (const float*)d_in[1];
    const float* edge_weight = (const float*)d_in[2];
    const int*   edge_dst    = (const int*)d_in[3];
    const int*   edge_src    = (const int*)d_in[4];
    float* out = (float*)d_out;

    const int E = in_sizes[3];

    // Zero the (poisoned) output
    int n4 = out_size / 4;
    tps_zero_kernel<<<(n4 + 255) / 256, 256>>>((float4*)out, n4);

    // One warp per edge
    int blocks = (E + WARPS_PER_BLOCK - 1) / WARPS_PER_BLOCK;
    tps_scatter_kernel<<<blocks, WARPS_PER_BLOCK * 32>>>(
        x, edge_attr, edge_weight, edge_dst, edge_src, out, E);
}